// round 13
// baseline (speedup 1.0000x reference)
#include <cuda_runtime.h>
#include <cstdint>

// Maxwell viscoelastic model, warp-parallel affine scan, FULL-ROW cp.async
// staging. R12 shape with CTA shrunk to 2 warps: 32 KB smem/CTA -> 7 CTAs/SM
// -> 14 warps x 16 KB = 224 KB of staged bytes in flight per SM (R12: 192 KB).
// Occupancy is irrelevant in this regime (R12 ran DRAM=82% at occ 16.5%);
// front-batched in-flight bytes is the only lever still moving the number.
//
//   gamma_{t+1} = A_t*gamma_t + B_t,  A_t = 1-2*dt_t, B_t = 2*dt_t*eps_t
//   out_0 = 0 ; out_t = eps_t + 2*(eps_t - gamma_t)
//
// Each warp stages its entire row (eps+dt, 16 KB) as 8 back-to-back cp.async
// groups, then consumes progressively with descending wait_group counts so
// chunk 0's compute overlaps the arrival of chunks 1..7.

#define TT    2048
#define EPI   256
#define NITER (TT / EPI)               // 8
#define WPB   2                        // warps per block
#define NTHREADS (WPB * 32)
#define DEPTH NITER                    // full row staged

// Stage layout per warp: [0..63] eps quads, [64..127] dt quads (float4).
#define STAGE_Q 128

__device__ __forceinline__ void cp16(float4* smem_dst, const float4* gmem_src) {
    uint32_t sa = (uint32_t)__cvta_generic_to_shared(smem_dst);
    asm volatile("cp.async.cg.shared.global [%0], [%1], 16;\n"
                 :: "r"(sa), "l"(gmem_src));
}
__device__ __forceinline__ void cp_commit() {
    asm volatile("cp.async.commit_group;\n");
}
template <int N>
__device__ __forceinline__ void cp_wait() {
    asm volatile("cp.async.wait_group %0;\n" :: "n"(N));
}

__global__ __launch_bounds__(NTHREADS, 7)
void maxwell_fullrow_v13(const float* __restrict__ eps_g,
                         const float* __restrict__ dt_g,
                         float* __restrict__ out_g) {
    __shared__ float4 sbuf[WPB][DEPTH][STAGE_Q];    // 32 KB

    const int lane = threadIdx.x & 31;
    const int warp = threadIdx.x >> 5;
    const int row  = blockIdx.x * WPB + warp;       // one row per warp
    const size_t base = (size_t)row * TT;

    const float4* eps4 = reinterpret_cast<const float4*>(eps_g + base);
    const float4* dt4  = reinterpret_cast<const float4*>(dt_g  + base);
    float4*       out4 = reinterpret_cast<float4*>(out_g + base);

    // Issue the WHOLE row as 8 back-to-back groups (front-batched MLP).
#pragma unroll
    for (int s = 0; s < DEPTH; ++s) {
        const int qb = s * 64;
        float4* st = sbuf[warp][s];
        cp16(&st[lane],           &eps4[qb + lane]);
        cp16(&st[lane + 32],      &eps4[qb + lane + 32]);
        cp16(&st[64 + lane],      &dt4[qb + lane]);
        cp16(&st[64 + lane + 32], &dt4[qb + lane + 32]);
        cp_commit();
    }

    float gamma_in = 0.0f;
    const int ql = 2 * lane;                        // lane's first quad

    auto do_chunk = [&](int it) {
        __syncwarp();                               // group landed for ALL lanes

        const float4* st = sbuf[warp][it];
        const float4 e0 = st[ql];
        const float4 e1 = st[ql + 1];
        const float4 d0 = st[64 + ql];
        const float4 d1 = st[64 + ql + 1];

        const float ee[8] = {e0.x, e0.y, e0.z, e0.w, e1.x, e1.y, e1.z, e1.w};
        const float td[8] = {d0.x + d0.x, d0.y + d0.y, d0.z + d0.z, d0.w + d0.w,
                             d1.x + d1.x, d1.y + d1.y, d1.z + d1.z, d1.w + d1.w};

        // Lane-local compose of 8 affine maps: (A,B) = m7 o ... o m0.
        float A = 1.0f - td[0];
        float B = td[0] * ee[0];
#pragma unroll
        for (int k = 1; k < 8; ++k) {
            const float Ak = 1.0f - td[k];
            const float Bk = td[k] * ee[k];
            B = fmaf(Ak, B, Bk);
            A = Ak * A;
        }

        // Inclusive Kogge-Stone scan of affine maps across the warp.
        float SA = A, SB = B;
#pragma unroll
        for (int dstep = 1; dstep < 32; dstep <<= 1) {
            const float pA = __shfl_up_sync(0xffffffffu, SA, dstep);
            const float pB = __shfl_up_sync(0xffffffffu, SB, dstep);
            if (lane >= dstep) {
                SB = fmaf(SA, pB, SB);
                SA = SA * pA;
            }
        }

        // Scalar-gamma epilogue: entry gamma + warp carry (2 shuffles).
        const float g_incl = fmaf(SA, gamma_in, SB);
        float g = __shfl_up_sync(0xffffffffu, g_incl, 1);
        if (lane == 0) g = gamma_in;
        gamma_in = __shfl_sync(0xffffffffu, g_incl, 31);

        // Apply: t = eps-gamma; sigma = eps + 2t; gamma += 2dt*t.
        float ss[8];
#pragma unroll
        for (int k = 0; k < 8; ++k) {
            const float t = ee[k] - g;
            ss[k] = fmaf(2.0f, t, ee[k]);
            g = fmaf(td[k], t, g);
        }

        if (it == 0 && lane == 0) ss[0] = 0.0f;     // out[0] = 0

        const int qo = it * 64 + ql;
        __stcs(&out4[qo],     make_float4(ss[0], ss[1], ss[2], ss[3]));
        __stcs(&out4[qo + 1], make_float4(ss[4], ss[5], ss[6], ss[7]));
    };

    // Progressive consumption: chunk c runs once <= (7-c) groups remain.
    cp_wait<7>(); do_chunk(0);
    cp_wait<6>(); do_chunk(1);
    cp_wait<5>(); do_chunk(2);
    cp_wait<4>(); do_chunk(3);
    cp_wait<3>(); do_chunk(4);
    cp_wait<2>(); do_chunk(5);
    cp_wait<1>(); do_chunk(6);
    cp_wait<0>(); do_chunk(7);
}

extern "C" void kernel_launch(void* const* d_in, const int* in_sizes, int n_in,
                              void* d_out, int out_size) {
    const float* strains = (const float*)d_in[0];
    const float* dts     = (const float*)d_in[1];
    float* out           = (float*)d_out;

    const int B = 16384;
    maxwell_fullrow_v13<<<B / WPB, NTHREADS>>>(strains, dts, out);
}